// round 1
// baseline (speedup 1.0000x reference)
#include <cuda_runtime.h>
#include <cstdint>

// Problem constants (match reference)
#define T_DIM     1024
#define SEQ_LEN   8192
#define STATE_LEN 4096

#define THREADS        256
#define ROWS_PER_BLOCK 8
#define VEC_ITERS      (SEQ_LEN / 4 / THREADS)   // 8 int4/float4 groups per thread
#define ELEMS_PER_THR  (SEQ_LEN / THREADS)        // 32

__global__ __launch_bounds__(THREADS)
void attn_time_kernel(const int* __restrict__ his,
                      const int* __restrict__ cur,
                      const float* __restrict__ mat,
                      float* __restrict__ out)
{
    __shared__ int   sh_his[SEQ_LEN];   // 32 KB, reused for all 8 rows
    __shared__ float tbl[T_DIM];        // 4 KB  exp table for current row
    __shared__ float red[THREADS / 32]; // warp partials

    const int tid  = threadIdx.x;
    const int lane = tid & 31;
    const int wid  = tid >> 5;

    // Stage his (same for every row) once per block, vectorized.
    {
        const int4* hg = reinterpret_cast<const int4*>(his);
        int4*       hs = reinterpret_cast<int4*>(sh_his);
        #pragma unroll
        for (int k = 0; k < VEC_ITERS; k++)
            hs[tid + k * THREADS] = hg[tid + k * THREADS];
    }
    __syncthreads();

    const int row0 = blockIdx.x * ROWS_PER_BLOCK;

    for (int r = 0; r < ROWS_PER_BLOCK; r++) {
        const int i = row0 + r;
        const float* rowp = mat + (size_t)cur[i] * T_DIM;

        // ---- Phase 1: load row (1024 fp32 = exactly one float4/thread), row max ----
        float4 rv = reinterpret_cast<const float4*>(rowp)[tid];
        float m = fmaxf(fmaxf(rv.x, rv.y), fmaxf(rv.z, rv.w));
        #pragma unroll
        for (int o = 16; o; o >>= 1)
            m = fmaxf(m, __shfl_xor_sync(0xffffffffu, m, o));
        if (lane == 0) red[wid] = m;
        __syncthreads();                    // red[] holds 8 warp maxima
        float bm = red[0];
        #pragma unroll
        for (int w = 1; w < THREADS / 32; w++) bm = fmaxf(bm, red[w]);

        // ---- Phase 2: exp table into smem (1024 exps/row, not 8192) ----
        float4 e;
        e.x = __expf(rv.x - bm);
        e.y = __expf(rv.y - bm);
        e.z = __expf(rv.z - bm);
        e.w = __expf(rv.w - bm);
        reinterpret_cast<float4*>(tbl)[tid] = e;
        __syncthreads();                    // tbl ready; red[] reads done above

        // ---- Phase 3: gather 32 values/thread from table, accumulate sum ----
        float v[ELEMS_PER_THR];
        float s = 0.0f;
        const int4* hs = reinterpret_cast<const int4*>(sh_his);
        #pragma unroll
        for (int k = 0; k < VEC_ITERS; k++) {
            int4 h = hs[tid + k * THREADS];
            float a = tbl[h.x];
            float b = tbl[h.y];
            float c = tbl[h.z];
            float d = tbl[h.w];
            v[4 * k + 0] = a;
            v[4 * k + 1] = b;
            v[4 * k + 2] = c;
            v[4 * k + 3] = d;
            s += (a + b) + (c + d);
        }
        #pragma unroll
        for (int o = 16; o; o >>= 1)
            s += __shfl_xor_sync(0xffffffffu, s, o);
        if (lane == 0) red[wid] = s;
        __syncthreads();
        float tot = 0.0f;
        #pragma unroll
        for (int w = 0; w < THREADS / 32; w++) tot += red[w];
        const float inv = 1.0f / tot;

        // ---- Phase 4: scaled, fully-coalesced float4 writes ----
        float4* op = reinterpret_cast<float4*>(out + (size_t)i * SEQ_LEN);
        #pragma unroll
        for (int k = 0; k < VEC_ITERS; k++) {
            float4 o4;
            o4.x = v[4 * k + 0] * inv;
            o4.y = v[4 * k + 1] * inv;
            o4.z = v[4 * k + 2] * inv;
            o4.w = v[4 * k + 3] * inv;
            op[tid + k * THREADS] = o4;
        }
        __syncthreads();                    // protect tbl/red before next row
    }
}

extern "C" void kernel_launch(void* const* d_in, const int* in_sizes, int n_in,
                              void* d_out, int out_size)
{
    const int*   his = (const int*)d_in[0];        // [8192] int32
    const int*   cur = (const int*)d_in[1];        // [4096] int32
    const float* mat = (const float*)d_in[2];      // [1024,1024] fp32
    float*       out = (float*)d_out;              // [4096,8192] fp32

    (void)in_sizes; (void)n_in; (void)out_size;

    dim3 grid(STATE_LEN / ROWS_PER_BLOCK);          // 512 blocks
    attn_time_kernel<<<grid, THREADS>>>(his, cur, mat, out);
}